// round 4
// baseline (speedup 1.0000x reference)
#include <cuda_runtime.h>
#include <cuda_bf16.h>

// Problem constants
#define NB   64            // batch
#define CC   128           // channels
#define TT   300           // time
#define VV   25            // vertices
#define KK   3             // adjacency count
#define TV   (TT*VV)       // 7500
#define CO   (CC*KK)       // 384 output channels of 1x1 conv
#define NROWS (NB*TV)      // 480000 GEMM rows
#define NELEM (NB*CC*TT*VV) // 61,440,000 output elems
#define BN_EPS 1e-5f

// ---------------- scratch (static device globals; no allocation allowed) ----
__device__ float g_y1[(size_t)NROWS * CO];   // intermediate conv output, [n,t,v,o]
__device__ float g_Wt[CC * CO];              // W transposed: [c][o]
__device__ float g_bias2[CC * VV];           // bias folded through A: [c][w]
__device__ float g_sum[CC];
__device__ float g_sumsq[CC];
__device__ float g_scale[CC];
__device__ float g_shift[CC];

// ---------------- kernel 0: prep (zero stats, transpose W, fold bias) ------
__global__ void prep_kernel(const float* __restrict__ W,
                            const float* __restrict__ b,
                            const float* __restrict__ A) {
    int tid = blockIdx.x * blockDim.x + threadIdx.x;
    int stride = gridDim.x * blockDim.x;
    if (blockIdx.x == 0 && threadIdx.x < CC) {
        g_sum[threadIdx.x] = 0.f;
        g_sumsq[threadIdx.x] = 0.f;
    }
    // transpose W (CO x CC) -> Wt (CC x CO)
    for (int i = tid; i < CC * CO; i += stride) {
        int c = i / CO, o = i % CO;
        g_Wt[i] = W[o * CC + c];
    }
    // bias2[c][w] = sum_k b[k*CC+c] * sum_v A[k,v,w]
    for (int i = tid; i < CC * VV; i += stride) {
        int c = i / VV, w = i % VV;
        float s = 0.f;
        #pragma unroll
        for (int k = 0; k < KK; k++) {
            float cs = 0.f;
            #pragma unroll
            for (int v = 0; v < VV; v++) cs += A[k * VV * VV + v * VV + w];
            s += b[k * CC + c] * cs;
        }
        g_bias2[i] = s;
    }
}

// ---------------- kernel 1: SGEMM  y1[(n,t,v), o] = x[(n,t,v), c] @ Wt -----
// Block tile 128 rows x 128 cols, K-step 8, 256 threads, 8x8 per thread.
__global__ void __launch_bounds__(256) gemm1_kernel(const float* __restrict__ x) {
    const int o0 = blockIdx.x * 128;       // 0,128,256
    const int r0 = blockIdx.y * 128;       // row tile within one n (0..58)
    const int n  = blockIdx.z;

    __shared__ float Xs[8][128];
    __shared__ float Ws[8][128];

    const int tid = threadIdx.x;
    const int lkk = tid >> 5;              // 0..7
    const int li4 = (tid & 31) << 2;       // 0,4,...,124
    const int tx = tid & 15;
    const int ty = tid >> 4;

    const float* xn = x + (size_t)n * CC * TV;

    float acc[8][8];
    #pragma unroll
    for (int i = 0; i < 8; i++)
        #pragma unroll
        for (int j = 0; j < 8; j++) acc[i][j] = 0.f;

    for (int c0 = 0; c0 < CC; c0 += 8) {
        // load X tile (rows are contiguous in (t,v))
        float4 xv = make_float4(0.f, 0.f, 0.f, 0.f);
        if (r0 + li4 < TV)
            xv = *(const float4*)(xn + (c0 + lkk) * TV + r0 + li4);
        *(float4*)&Xs[lkk][li4] = xv;
        // load W tile (Wt row-contiguous in o)
        *(float4*)&Ws[lkk][li4] = *(const float4*)(g_Wt + (c0 + lkk) * CO + o0 + li4);
        __syncthreads();

        #pragma unroll
        for (int kk = 0; kk < 8; kk++) {
            float a_[8], b_[8];
            *(float4*)&a_[0] = *(float4*)&Xs[kk][ty * 8];
            *(float4*)&a_[4] = *(float4*)&Xs[kk][ty * 8 + 4];
            *(float4*)&b_[0] = *(float4*)&Ws[kk][tx * 8];
            *(float4*)&b_[4] = *(float4*)&Ws[kk][tx * 8 + 4];
            #pragma unroll
            for (int i = 0; i < 8; i++)
                #pragma unroll
                for (int j = 0; j < 8; j++)
                    acc[i][j] = fmaf(a_[i], b_[j], acc[i][j]);
        }
        __syncthreads();
    }

    // epilogue: y1[(n*TV + r) * CO + o]
    #pragma unroll
    for (int i = 0; i < 8; i++) {
        int r = r0 + ty * 8 + i;
        if (r < TV) {
            float* dst = g_y1 + (size_t)(n * TV + r) * CO + o0 + tx * 8;
            float4 v0 = make_float4(acc[i][0], acc[i][1], acc[i][2], acc[i][3]);
            float4 v1 = make_float4(acc[i][4], acc[i][5], acc[i][6], acc[i][7]);
            *(float4*)dst = v0;
            *(float4*)(dst + 4) = v1;
        }
    }
}

// ---------------- kernel 2: adjacency agg + bias + residual + relu + stats -
#define T_PER_BLK 10
__global__ void __launch_bounds__(128) aggregate_kernel(const float* __restrict__ x,
                                                        const float* __restrict__ A,
                                                        float* __restrict__ out) {
    const int n = blockIdx.y;
    const int tblk = blockIdx.x;
    const int c = threadIdx.x;   // channel

    __shared__ float A_s[KK * VV * 28];   // padded rows of 28 floats (16B aligned)
    __shared__ float bias_s[CC * VV];

    for (int i = c; i < KK * VV * VV; i += CC) {
        int k = i / (VV * VV), rem = i % (VV * VV);
        int v = rem / VV, w = rem % VV;
        A_s[(k * VV + v) * 28 + w] = A[i];
    }
    for (int i = c; i < CC * VV; i += CC) bias_s[i] = g_bias2[i];
    __syncthreads();

    float bsum = 0.f, bsq = 0.f;

    for (int tt = 0; tt < T_PER_BLK; tt++) {
        const int t = tblk * T_PER_BLK + tt;
        float accv[VV];
        #pragma unroll
        for (int w = 0; w < VV; w++) accv[w] = bias_s[c * VV + w];

        const float* yb = g_y1 + (size_t)((n * TT + t) * VV) * CO + c;
        #pragma unroll
        for (int k = 0; k < KK; k++) {
            #pragma unroll
            for (int v = 0; v < VV; v++) {
                float yv = yb[v * CO + k * CC];           // coalesced over c
                const float* Ar = &A_s[(k * VV + v) * 28];
                #pragma unroll
                for (int w = 0; w < VV; w++)
                    accv[w] = fmaf(yv, Ar[w], accv[w]);
            }
        }

        const float* xr = x + (size_t)((n * CC + c) * TT + t) * VV;
        float* orow = out + (size_t)((n * CC + c) * TT + t) * VV;
        #pragma unroll
        for (int w = 0; w < VV; w++) {
            float yv = accv[w] + xr[w];
            yv = fmaxf(yv, 0.f);
            orow[w] = yv;
            bsum += yv;
            bsq += yv * yv;
        }
    }
    atomicAdd(&g_sum[c], bsum);
    atomicAdd(&g_sumsq[c], bsq);
}

// ---------------- kernel 3: fold BN stats into per-channel scale/shift -----
__global__ void stats_kernel(const float* __restrict__ gamma,
                             const float* __restrict__ beta) {
    int c = threadIdx.x;
    const float inv = 1.f / (float)(NB * TT * VV);
    float mean = g_sum[c] * inv;
    float var = g_sumsq[c] * inv - mean * mean;
    float sc = gamma[c] * rsqrtf(var + BN_EPS);
    g_scale[c] = sc;
    g_shift[c] = beta[c] - mean * sc;
}

// ---------------- kernel 4: in-place normalize + A passthrough tail --------
__global__ void normalize_kernel(float* __restrict__ out,
                                 const float* __restrict__ A,
                                 int out_size) {
    const int total4 = NELEM / 4;
    int stride = gridDim.x * blockDim.x;
    for (int idx = blockIdx.x * blockDim.x + threadIdx.x; idx < total4; idx += stride) {
        int e = idx * 4;
        int c = (e / TV) % CC;   // 4-aligned, TV%4==0 -> same c for all 4
        float sc = g_scale[c], sh = g_shift[c];
        float4 v = ((float4*)out)[idx];
        v.x = fmaf(v.x, sc, sh);
        v.y = fmaf(v.y, sc, sh);
        v.z = fmaf(v.z, sc, sh);
        v.w = fmaf(v.w, sc, sh);
        ((float4*)out)[idx] = v;
    }
    // reference returns (out, A): copy A into the tail if the harness expects it
    if (out_size > NELEM) {
        int tail = out_size - NELEM;  // expected KK*VV*VV = 1875
        for (int j = blockIdx.x * blockDim.x + threadIdx.x; j < tail && j < KK * VV * VV;
             j += stride)
            out[NELEM + j] = A[j];
    }
}

// ---------------- launch ----------------------------------------------------
extern "C" void kernel_launch(void* const* d_in, const int* in_sizes, int n_in,
                              void* d_out, int out_size) {
    const float* x     = (const float*)d_in[0];
    const float* A     = (const float*)d_in[1];
    const float* W     = (const float*)d_in[2];
    const float* b     = (const float*)d_in[3];
    const float* gamma = (const float*)d_in[4];
    const float* beta  = (const float*)d_in[5];
    float* out = (float*)d_out;

    prep_kernel<<<64, 256>>>(W, b, A);

    dim3 g1(CO / 128, (TV + 127) / 128, NB);   // (3, 59, 64)
    gemm1_kernel<<<g1, 256>>>(x);

    dim3 g2(TT / T_PER_BLK, NB);               // (30, 64)
    aggregate_kernel<<<g2, 128>>>(x, A, out);

    stats_kernel<<<1, CC>>>(gamma, beta);

    normalize_kernel<<<2048, 256>>>(out, A, out_size);
}